// round 16
// baseline (speedup 1.0000x reference)
#include <cuda_runtime.h>
#include <math.h>

// Problem constants (fixed by the dataset instance)
#define V     32000
#define H     1024
#define H4    256
#define SLEN  256
#define MAXL  64
#define BEAM  4

#define GRID  128
#define NT    512
#define NWARP 16
#define TOTW  (GRID*NWARP)   // 2048 warps
#define NGRP  8
#define GSZ   16             // blocks per barrier group (128/8)

// ---------------- persistent device state (no allocations) -------------------
__device__ float g_Xenc[SLEN*3*H];
__device__ float g_enc_out[SLEN*H];
__device__ float g_E2T[H*SLEN];        // E2T[j][t] = Wc_ctx[j] . enc_out[t]
__device__ float g_h[BEAM*H];
__device__ float g_hnew[BEAM*H];
__device__ float g_cc[BEAM*H];
__device__ float g_scores[BEAM*SLEN];
__device__ float g_pm[BEAM*GRID];
__device__ float g_ps[BEAM*GRID];
__device__ float g_ptv[BEAM*GRID*4];
__device__ int   g_pti[BEAM*GRID*4];
__device__ float g_cum[BEAM];          // block-0 private
__device__ int   g_inputs[BEAM];
__device__ int   g_tokens[BEAM*MAXL];
__device__ float g_shist[BEAM*MAXL];
__device__ unsigned g_grp[NGRP];
__device__ unsigned g_root;
__device__ unsigned g_gen;

// ---------------- helpers ----------------------------------------------------
__device__ __forceinline__ float wred(float v){
    #pragma unroll
    for(int o=16;o>0;o>>=1) v += __shfl_xor_sync(0xffffffffu, v, o);
    return v;
}
__device__ __forceinline__ float wmax(float v){
    #pragma unroll
    for(int o=16;o>0;o>>=1) v = fmaxf(v, __shfl_xor_sync(0xffffffffu, v, o));
    return v;
}
__device__ __forceinline__ bool better(float v1,int i1,float v2,int i2){
    return (v1>v2) || (v1==v2 && i1<i2);   // jax top_k: value desc, index asc
}
__device__ __forceinline__ void ins4(float* tv,int* ti,float x,int i){
    if(better(x,i,tv[3],ti[3])){
        tv[3]=x; ti[3]=i;
        #pragma unroll
        for(int k=3;k>0;k--){
            if(better(tv[k],ti[k],tv[k-1],ti[k-1])){
                float tf=tv[k]; tv[k]=tv[k-1]; tv[k-1]=tf;
                int   t2=ti[k]; ti[k]=ti[k-1]; ti[k-1]=t2;
            }
        }
    }
}
__device__ __forceinline__ void merge4r(float* av,int* ai,const float* bv,const int* bi){
    float ov[4]; int oi[4]; int ia=0, ib=0;
    #pragma unroll
    for(int k=0;k<4;k++){
        if(better(av[ia],ai[ia],bv[ib],bi[ib])){ ov[k]=av[ia]; oi[k]=ai[ia]; ia++; }
        else                                   { ov[k]=bv[ib]; oi[k]=bi[ib]; ib++; }
    }
    #pragma unroll
    for(int k=0;k<4;k++){ av[k]=ov[k]; ai[k]=oi[k]; }
}
__device__ __forceinline__ void merge4(float* tvv,int* tii,int a,int c){
    float av[4],bv[4]; int ai[4],bi[4];
    #pragma unroll
    for(int k=0;k<4;k++){ av[k]=tvv[a*4+k]; ai[k]=tii[a*4+k];
                          bv[k]=tvv[c*4+k]; bi[k]=tii[c*4+k]; }
    merge4r(av,ai,bv,bi);
    #pragma unroll
    for(int k=0;k<4;k++){ tvv[a*4+k]=av[k]; tii[a*4+k]=ai[k]; }
}

// Two-level tree barrier, fence-free. Local generation counter: no acquire
// load on the arrival path; target generation tracked in a register.
// Safe: root releases gen N only after ALL blocks arrived at barrier N, and
// every block captures its base before its own first arrival.
__device__ __forceinline__ void gbar(unsigned &mygen){
    __syncthreads();
    mygen++;
    if(threadIdx.x==0){
        unsigned t;
        asm volatile("atom.acq_rel.gpu.global.add.u32 %0,[%1],%2;"
                     : "=r"(t) : "l"(&g_grp[blockIdx.x & (NGRP-1)]), "r"(1u) : "memory");
        if(t == (unsigned)(GSZ-1)){
            unsigned r;
            asm volatile("atom.acq_rel.gpu.global.add.u32 %0,[%1],%2;"
                         : "=r"(r) : "l"(&g_root), "r"(1u) : "memory");
            if(r == (unsigned)(NGRP-1)){
                asm volatile("st.relaxed.gpu.global.u32 [%0],%1;"
                             :: "l"(&g_root), "r"(0u) : "memory");
                #pragma unroll
                for(int i=0;i<NGRP;i++)
                    asm volatile("st.relaxed.gpu.global.u32 [%0],%1;"
                                 :: "l"(&g_grp[i]), "r"(0u) : "memory");
                asm volatile("red.release.gpu.global.add.u32 [%0],%1;"
                             :: "l"(&g_gen), "r"(1u) : "memory");
            }
        }
        unsigned cur;
        for(;;){
            asm volatile("ld.acquire.gpu.global.u32 %0,[%1];"
                         : "=r"(cur) : "l"(&g_gen) : "memory");
            if((int)(cur - mygen) >= 0) break;
        }
    }
    __syncthreads();
}

// ---------------- the persistent kernel --------------------------------------
__global__ void __launch_bounds__(NT,1)
beam_kernel(const int* __restrict__ input_seq,
            const float* __restrict__ emb,
            const float* __restrict__ eWih, const float* __restrict__ eWhh,
            const float* __restrict__ ebih, const float* __restrict__ ebhh,
            const float* __restrict__ dWih, const float* __restrict__ dWhh,
            const float* __restrict__ dbih, const float* __restrict__ dbhh,
            const float* __restrict__ Wc,   const float* __restrict__ Wout,
            int L, float* __restrict__ out)
{
    __shared__ __align__(16) float s_buf[9472];   // 37KB multipurpose
    __shared__ float s_red[512];
    __shared__ float s_part[192];    // D1 partials
    __shared__ float s_p34[64];      // D34 partials
    __shared__ float s_d2[16];       // D2 partials
    __shared__ float s_M4[4], s_S4[4];
    __shared__ int   sh_bi[4], sh_jj[4], sh_tok[4];
    __shared__ float sh_ss[4];
    __shared__ float s_tpv[16];
    __shared__ int   s_tiv[16];
    __shared__ int   s_inp[4];
    __shared__ int   s_best;

    const int tid  = threadIdx.x;
    const int lane = tid & 31;
    const int w    = tid >> 5;                 // 0..15
    const int gw   = blockIdx.x * NWARP + w;   // 0..2047

    // capture barrier generation base (before first gbar arrival)
    unsigned mygen = 0;
    if(tid==0){
        asm volatile("ld.acquire.gpu.global.u32 %0,[%1];"
                     : "=r"(mygen) : "l"(&g_gen) : "memory");
    }

    // ===== Phase 0: g_Xenc[t][k] = emb[seq[t]] . eWih[k] + ebih[k] ==========
    {
        int tgrp  = blockIdx.x & 31;
        int kpart = blockIdx.x >> 5;
        int t0 = tgrp*8;
        for(int idx=tid; idx<8*H; idx+=NT){
            int tt = idx>>10, c = idx&(H-1);
            s_buf[idx] = emb[(size_t)input_seq[t0+tt]*H + c];
        }
        __syncthreads();
        const float4* xs4 = (const float4*)s_buf;
        int kbeg = kpart*768, kend = kbeg+768;
        for(int k=kbeg+w; k<kend; k+=NWARP){
            const float4* wr = (const float4*)(eWih + (size_t)k*H);
            float acc[8] = {0,0,0,0,0,0,0,0};
            #pragma unroll
            for(int i=0;i<8;i++){
                float4 wv = wr[lane+32*i];
                #pragma unroll
                for(int tt=0;tt<8;tt++){
                    float4 xv = xs4[tt*H4 + lane + 32*i];
                    acc[tt]=fmaf(wv.x,xv.x,acc[tt]); acc[tt]=fmaf(wv.y,xv.y,acc[tt]);
                    acc[tt]=fmaf(wv.z,xv.z,acc[tt]); acc[tt]=fmaf(wv.w,xv.w,acc[tt]);
                }
            }
            #pragma unroll
            for(int tt=0;tt<8;tt++){
                float r = wred(acc[tt]);
                if(lane==0) g_Xenc[(size_t)(t0+tt)*3*H + k] = r + ebih[k];
            }
        }
    }
    gbar(mygen);

    // ===== Encoder recurrence (warps 0-7 active; j = blockIdx*8+w) ==========
    {
        const int j = blockIdx.x*8 + (w&7);
        const bool enc_act = (w < 8);
        const float4* w0 = (const float4*)(eWhh + (size_t)j*H);
        const float4* w1 = (const float4*)(eWhh + (size_t)(H+j)*H);
        const float4* w2 = (const float4*)(eWhh + (size_t)(2*H+j)*H);
        const float b0 = ebhh[j], b1 = ebhh[H+j], b2 = ebhh[2*H+j];
        float4* s_h4 = (float4*)s_buf;
        const float* s_hf = s_buf;
        float gi0 = g_Xenc[j];
        float gi1 = g_Xenc[H + j];
        float gi2 = g_Xenc[2*H + j];
        for(int t=0;t<SLEN;t++){
            if(tid < 256){
                if(t==0) s_h4[tid] = make_float4(0.f,0.f,0.f,0.f);
                else     s_h4[tid] = __ldcg(((const float4*)(g_enc_out + (size_t)(t-1)*H)) + tid);
            }
            __syncthreads();
            if(enc_act){
                float a0=0.f, a1=0.f, a2=0.f;
                #pragma unroll
                for(int k=0;k<8;k++){
                    int i = lane + 32*k;
                    float4 hv = s_h4[i];
                    float4 v0 = w0[i], v1 = w1[i], v2 = w2[i];
                    a0=fmaf(v0.x,hv.x,a0); a0=fmaf(v0.y,hv.y,a0); a0=fmaf(v0.z,hv.z,a0); a0=fmaf(v0.w,hv.w,a0);
                    a1=fmaf(v1.x,hv.x,a1); a1=fmaf(v1.y,hv.y,a1); a1=fmaf(v1.z,hv.z,a1); a1=fmaf(v1.w,hv.w,a1);
                    a2=fmaf(v2.x,hv.x,a2); a2=fmaf(v2.y,hv.y,a2); a2=fmaf(v2.z,hv.z,a2); a2=fmaf(v2.w,hv.w,a2);
                }
                a0 = wred(a0); a1 = wred(a1); a2 = wred(a2);
                if(lane==0){
                    float hp = s_hf[j];
                    float r = 1.f/(1.f+expf(-(gi0 + a0 + b0)));
                    float z = 1.f/(1.f+expf(-(gi1 + a1 + b1)));
                    float n = tanhf(gi2 + r*(a2 + b2));
                    g_enc_out[(size_t)t*H + j] = (1.f-z)*n + z*hp;
                }
            }
            float n0=0.f, n1=0.f, n2=0.f;
            if(t+1<SLEN){
                n0 = g_Xenc[(size_t)(t+1)*3*H + j];
                n1 = g_Xenc[(size_t)(t+1)*3*H + H + j];
                n2 = g_Xenc[(size_t)(t+1)*3*H + 2*H + j];
            }
            gbar(mygen);
            gi0=n0; gi1=n1; gi2=n2;
        }
    }

    // ===== E2T precompute: E2T[j][t] = Wc_ctx[j] . enc_out[t] ===============
    {
        const int j = blockIdx.x*8 + (w&7);
        const int tt0 = (w>>3)*4;
        const float4* wr = (const float4*)(Wc + (size_t)j*2*H + H);
        for(int tile=0; tile<32; tile++){
            for(int i4=tid; i4<2048; i4+=NT)
                ((float4*)s_buf)[i4] =
                    __ldcg(((const float4*)(g_enc_out + (size_t)tile*8*H)) + i4);
            __syncthreads();
            #pragma unroll
            for(int q=0; q<4; q++){
                int tt = tt0 + q;
                const float4* er = ((const float4*)s_buf) + tt*256;
                float a = 0.f;
                #pragma unroll
                for(int k=0;k<8;k++){
                    int i = lane + 32*k;
                    float4 wv = wr[i], ev = er[i];
                    a=fmaf(wv.x,ev.x,a); a=fmaf(wv.y,ev.y,a);
                    a=fmaf(wv.z,ev.z,a); a=fmaf(wv.w,ev.w,a);
                }
                a = wred(a);
                if(lane==0) g_E2T[(size_t)j*SLEN + tile*8 + tt] = a;
            }
            __syncthreads();
        }
    }

    // ===== Init beam state ==================================================
    {
        int idx = blockIdx.x*NT + tid;
        if(idx < BEAM*H) g_h[idx] = __ldcg(&g_enc_out[(size_t)(SLEN-1)*H + (idx&(H-1))]);
        if(blockIdx.x==0 && tid<BEAM){ g_cum[tid]=0.f; g_inputs[tid]=1; /*SOS*/ }
    }
    gbar(mygen);

    // ===== Decoder loop =====================================================
    for(int step=0; step<L; step++){
        // ---- D1: GRU cell. warp-pair split: w<8 input-proj, w>=8 hidden ----
        {
            if(tid<4) s_inp[tid] = __ldcg(&g_inputs[tid]);
            __syncthreads();
            float4* s_x4 = (float4*)s_buf;
            float4* s_h4 = ((float4*)s_buf) + 1024;
            for(int i4=tid; i4<1024; i4+=NT){
                int b = i4>>8, c = i4&255;
                s_x4[i4] = ((const float4*)(emb + (size_t)s_inp[b]*H))[c];
                s_h4[i4] = __ldcg(((const float4*)g_h) + i4);
            }
            __syncthreads();
            const int jl = w&7;
            const int j  = blockIdx.x*8 + jl;
            const int half = w>>3;
            const float* Wsrc = half ? dWhh : dWih;
            const float4* src = half ? s_h4 : s_x4;
            const float4* r0 = (const float4*)(Wsrc + (size_t)j*H);
            const float4* r1 = (const float4*)(Wsrc + (size_t)(H+j)*H);
            const float4* r2 = (const float4*)(Wsrc + (size_t)(2*H+j)*H);
            float a0[4]={0,0,0,0}, a1[4]={0,0,0,0}, a2[4]={0,0,0,0};
            #pragma unroll
            for(int k=0;k<8;k++){
                int i = lane + 32*k;
                float4 u0=r0[i], u1=r1[i], u2=r2[i];
                #pragma unroll
                for(int b=0;b<4;b++){
                    float4 xv = src[b*256+i];
                    a0[b]=fmaf(u0.x,xv.x,a0[b]); a0[b]=fmaf(u0.y,xv.y,a0[b]); a0[b]=fmaf(u0.z,xv.z,a0[b]); a0[b]=fmaf(u0.w,xv.w,a0[b]);
                    a1[b]=fmaf(u1.x,xv.x,a1[b]); a1[b]=fmaf(u1.y,xv.y,a1[b]); a1[b]=fmaf(u1.z,xv.z,a1[b]); a1[b]=fmaf(u1.w,xv.w,a1[b]);
                    a2[b]=fmaf(u2.x,xv.x,a2[b]); a2[b]=fmaf(u2.y,xv.y,a2[b]); a2[b]=fmaf(u2.z,xv.z,a2[b]); a2[b]=fmaf(u2.w,xv.w,a2[b]);
                }
            }
            #pragma unroll
            for(int b=0;b<4;b++){ a0[b]=wred(a0[b]); a1[b]=wred(a1[b]); a2[b]=wred(a2[b]); }
            if(lane==0){
                int base = jl*24 + half*12;
                #pragma unroll
                for(int b=0;b<4;b++){
                    s_part[base +      b] = a0[b];
                    s_part[base + 4  + b] = a1[b];
                    s_part[base + 8  + b] = a2[b];
                }
            }
            __syncthreads();
            if(tid < 32){
                int jl2 = tid>>2, b = tid&3;
                int j2 = blockIdx.x*8 + jl2;
                int ib = jl2*24, hb = jl2*24+12;
                float gi0 = s_part[ib+b]      + dbih[j2];
                float gi1 = s_part[ib+4+b]    + dbih[H+j2];
                float gi2 = s_part[ib+8+b]    + dbih[2*H+j2];
                float gh0 = s_part[hb+b]      + dbhh[j2];
                float gh1 = s_part[hb+4+b]    + dbhh[H+j2];
                float gh2 = s_part[hb+8+b]    + dbhh[2*H+j2];
                float r = 1.f/(1.f+expf(-(gi0+gh0)));
                float z = 1.f/(1.f+expf(-(gi1+gh1)));
                float n = tanhf(gi2 + r*gh2);
                float hp = s_buf[4096 + b*1024 + j2];
                g_hnew[b*H+j2] = (1.f-z)*n + z*hp;
            }
        }
        gbar(mygen);
        // ---- D2: attention scores. 2 warps per (b,t), half-dot each --------
        {
            for(int i4=tid; i4<1024; i4+=NT)
                ((float4*)s_buf)[i4] = __ldcg(((const float4*)g_hnew) + i4);
            __syncthreads();
            int task = blockIdx.x*8 + (w&7);
            int b = task>>8, t = task&(SLEN-1);
            int half = w>>3;
            const float4* hn = ((const float4*)s_buf) + b*256;
            const float4* ev = (const float4*)(g_enc_out + (size_t)t*H);
            float s = 0.f;
            #pragma unroll
            for(int kk=0;kk<4;kk++){
                int i = lane + 32*(half*4 + kk);
                float4 a = hn[i]; float4 e = ev[i];
                s=fmaf(a.x,e.x,s); s=fmaf(a.y,e.y,s);
                s=fmaf(a.z,e.z,s); s=fmaf(a.w,e.w,s);
            }
            s = wred(s);
            if(lane==0) s_d2[w] = s;
            __syncthreads();
            if(w<8 && lane==0) g_scores[task] = s_d2[w] + s_d2[w+8];
        }
        gbar(mygen);
        // ---- D34: softmax (warps 0-3) + cc split across warp pairs ---------
        {
            float4* s_hn4 = (float4*)s_buf;
            float*  s_at  = s_buf + 4096;
            for(int i4=tid; i4<1024; i4+=NT)
                s_hn4[i4] = __ldcg(((const float4*)g_hnew) + i4);
            if(w < 4){
                int b = w;
                float x[8]; float m = -INFINITY;
                #pragma unroll
                for(int q=0;q<8;q++){
                    x[q] = __ldcg(&g_scores[b*SLEN + lane + 32*q]);
                    m = fmaxf(m, x[q]);
                }
                m = wmax(m);
                float ssum = 0.f; float e[8];
                #pragma unroll
                for(int q=0;q<8;q++){ e[q] = expf(x[q]-m); ssum += e[q]; }
                ssum = wred(ssum);
                float inv = 1.f/ssum;
                #pragma unroll
                for(int q=0;q<8;q++) s_at[b*SLEN + lane + 32*q] = e[q]*inv;
            }
            __syncthreads();
            const int jl = w&7;
            const int j  = blockIdx.x*8 + jl;
            const int half = w>>3;
            const float4* wh = (const float4*)(Wc + (size_t)j*2*H);
            const float4* e2 = (const float4*)(g_E2T + (size_t)j*SLEN);
            const float4* at4 = (const float4*)s_at;
            float acc[4] = {0,0,0,0};
            if(half==0){
                #pragma unroll
                for(int k=0;k<5;k++){
                    int i = lane + 32*k;
                    float4 wl = wh[i];
                    #pragma unroll
                    for(int b=0;b<4;b++){
                        float4 hv = s_hn4[b*256+i];
                        acc[b]=fmaf(wl.x,hv.x,acc[b]); acc[b]=fmaf(wl.y,hv.y,acc[b]);
                        acc[b]=fmaf(wl.z,hv.z,acc[b]); acc[b]=fmaf(wl.w,hv.w,acc[b]);
                    }
                }
            }else{
                #pragma unroll
                for(int k=5;k<8;k++){
                    int i = lane + 32*k;
                    float4 wl = wh[i];
                    #pragma unroll
                    for(int b=0;b<4;b++){
                        float4 hv = s_hn4[b*256+i];
                        acc[b]=fmaf(wl.x,hv.x,acc[b]); acc[b]=fmaf(wl.y,hv.y,acc[b]);
                        acc[b]=fmaf(wl.z,hv.z,acc[b]); acc[b]=fmaf(wl.w,hv.w,acc[b]);
                    }
                }
                #pragma unroll
                for(int k=0;k<2;k++){
                    int i = lane + 32*k;
                    float4 ev = e2[i];
                    #pragma unroll
                    for(int b=0;b<4;b++){
                        float4 av = at4[b*64+i];
                        acc[b]=fmaf(ev.x,av.x,acc[b]); acc[b]=fmaf(ev.y,av.y,acc[b]);
                        acc[b]=fmaf(ev.z,av.z,acc[b]); acc[b]=fmaf(ev.w,av.w,acc[b]);
                    }
                }
            }
            #pragma unroll
            for(int b=0;b<4;b++) acc[b] = wred(acc[b]);
            if(lane==0){
                #pragma unroll
                for(int b=0;b<4;b++) s_p34[w*4+b] = acc[b];
            }
            __syncthreads();
            if(w<8 && lane<4)
                g_cc[lane*H + j] = tanhf(s_p34[w*4+lane] + s_p34[(w+8)*4+lane]);
        }
        gbar(mygen);
        // ---- D5: logits GEMV. Rows p<5 (80MB) L2-resident via ldg;
        //          rows p>=5 (46MB) streamed via ldcs --------------------------
        for(int i4=tid; i4<BEAM*H4; i4+=NT)
            ((float4*)s_buf)[i4] = __ldcg(((const float4*)g_cc)+i4);
        __syncthreads();
        {
            const float4* c0 = (const float4*)s_buf;
            const float4* c1 = c0 + H4;
            const float4* c2 = c0 + 2*H4;
            const float4* c3 = c0 + 3*H4;
            float* s_lg = s_buf + 4096;
            int*   s_vi = (int*)(s_buf + 5120);
            for(int p=0;p<8;p++){
                int va = gw + p*(2*TOTW);
                int vb = va + TOTW;
                bool hasB = (vb < V);
                const float4* wa = (const float4*)(Wout + (size_t)va*H);
                const float4* wb = (const float4*)(Wout + (size_t)(hasB ? vb : va)*H);
                float4 A[8], B[8];
                if(p < 5){   // resident region: rows [0,20480) = 80MB, stays in L2
                    #pragma unroll
                    for(int k=0;k<8;k++) A[k] = __ldg(wa + lane + 32*k);
                    #pragma unroll
                    for(int k=0;k<8;k++) B[k] = __ldg(wb + lane + 32*k);
                }else{       // streaming region: evict-first, no L2 pollution
                    #pragma unroll
                    for(int k=0;k<8;k++) A[k] = __ldcs(wa + lane + 32*k);
                    #pragma unroll
                    for(int k=0;k<8;k++) B[k] = __ldcs(wb + lane + 32*k);
                }
                float a0=0.f,a1=0.f,a2=0.f,a3=0.f;
                float e0=0.f,e1=0.f,e2=0.f,e3=0.f;
                #pragma unroll
                for(int k=0;k<8;k++){
                    int i = lane + 32*k;
                    float4 u = A[k], vv = B[k];
                    float4 x0=c0[i],x1=c1[i],x2=c2[i],x3=c3[i];
                    a0=fmaf(u.x,x0.x,a0); a0=fmaf(u.y,x0.y,a0); a0=fmaf(u.z,x0.z,a0); a0=fmaf(u.w,x0.w,a0);
                    a1=fmaf(u.x,x1.x,a1); a1=fmaf(u.y,x1.y,a1); a1=fmaf(u.z,x1.z,a1); a1=fmaf(u.w,x1.w,a1);
                    a2=fmaf(u.x,x2.x,a2); a2=fmaf(u.y,x2.y,a2); a2=fmaf(u.z,x2.z,a2); a2=fmaf(u.w,x2.w,a2);
                    a3=fmaf(u.x,x3.x,a3); a3=fmaf(u.y,x3.y,a3); a3=fmaf(u.z,x3.z,a3); a3=fmaf(u.w,x3.w,a3);
                    e0=fmaf(vv.x,x0.x,e0); e0=fmaf(vv.y,x0.y,e0); e0=fmaf(vv.z,x0.z,e0); e0=fmaf(vv.w,x0.w,e0);
                    e1=fmaf(vv.x,x1.x,e1); e1=fmaf(vv.y,x1.y,e1); e1=fmaf(vv.z,x1.z,e1); e1=fmaf(vv.w,x1.w,e1);
                    e2=fmaf(vv.x,x2.x,e2); e2=fmaf(vv.y,x2.y,e2); e2=fmaf(vv.z,x2.z,e2); e2=fmaf(vv.w,x2.w,e2);
                    e3=fmaf(vv.x,x3.x,e3); e3=fmaf(vv.y,x3.y,e3); e3=fmaf(vv.z,x3.z,e3); e3=fmaf(vv.w,x3.w,e3);
                }
                a0=wred(a0); a1=wred(a1); a2=wred(a2); a3=wred(a3);
                e0=wred(e0); e1=wred(e1); e2=wred(e2); e3=wred(e3);
                if(lane==0){
                    int sA = w*16 + 2*p, sB = sA+1;
                    s_lg[      sA]=a0; s_lg[256+sA]=a1; s_lg[512+sA]=a2; s_lg[768+sA]=a3;
                    s_vi[sA]=va;
                    if(hasB){
                        s_lg[      sB]=e0; s_lg[256+sB]=e1; s_lg[512+sB]=e2; s_lg[768+sB]=e3;
                        s_vi[sB]=vb;
                    }else{
                        s_lg[      sB]=-INFINITY; s_lg[256+sB]=-INFINITY;
                        s_lg[512+sB]=-INFINITY;   s_lg[768+sB]=-INFINITY;
                        s_vi[sB]=0x7fffffff;
                    }
                }
            }
        }
        __syncthreads();
        // block-local per-beam reduce: 128 threads/beam over 256 slots -------
        {
            int b  = tid >> 7;
            int i0 = tid & 127;
            float* s_lg = s_buf + 4096;
            int*   s_vi = (int*)(s_buf + 5120);
            float* tvv  = s_buf + 5376;
            int*   tii  = (int*)(s_buf + 7424);
            float x1v = s_lg[b*256 + i0];
            float x2v = s_lg[b*256 + i0 + 128];
            int   v1 = s_vi[i0], v2 = s_vi[i0+128];
            s_red[tid] = fmaxf(x1v, x2v); __syncthreads();
            for(int off=64;off>0;off>>=1){
                if(i0<off) s_red[tid] = fmaxf(s_red[tid], s_red[tid+off]);
                __syncthreads();
            }
            float bmax = s_red[b*128];
            __syncthreads();
            float tv[4] = {-INFINITY,-INFINITY,-INFINITY,-INFINITY};
            int   tix[4]= {0x7fffffff,0x7fffffff,0x7fffffff,0x7fffffff};
            ins4(tv, tix, x1v, v1);
            ins4(tv, tix, x2v, v2);
            s_red[tid] = expf(x1v - bmax) + expf(x2v - bmax);
            #pragma unroll
            for(int k=0;k<4;k++){ tvv[tid*4+k]=tv[k]; tii[tid*4+k]=tix[k]; }
            __syncthreads();
            for(int off=64;off>0;off>>=1){
                if(i0<off){
                    s_red[tid] += s_red[tid+off];
                    merge4(tvv, tii, tid, tid+off);
                }
                __syncthreads();
            }
            if(i0==0){
                int pidx = b*GRID + blockIdx.x;
                g_pm[pidx] = bmax;
                g_ps[pidx] = s_red[tid];
                #pragma unroll
                for(int k=0;k<4;k++){
                    g_ptv[pidx*4+k] = tvv[tid*4+k];
                    g_pti[pidx*4+k] = tii[tid*4+k];
                }
            }
        }
        gbar(mygen);
        // ---- D6+D7: block 0 merges 512 partials (1/thread) + combine -------
        if(blockIdx.x==0){
            int b  = tid >> 7;
            int i0 = tid & 127;
            float* tvv = s_buf;
            int*   tii = (int*)(s_buf + 2048);
            int pidx = b*GRID + i0;
            float m = __ldcg(&g_pm[pidx]);
            float s = __ldcg(&g_ps[pidx]);
            #pragma unroll
            for(int k=0;k<4;k++){
                tvv[tid*4+k] = __ldcg(&g_ptv[pidx*4+k]);
                tii[tid*4+k] = __ldcg(&g_pti[pidx*4+k]);
            }
            s_red[tid] = m; __syncthreads();
            for(int off=64;off>0;off>>=1){
                if(i0<off) s_red[tid] = fmaxf(s_red[tid], s_red[tid+off]);
                __syncthreads();
            }
            if(i0==0) s_M4[b] = s_red[b*128];
            __syncthreads();
            float M = s_M4[b];
            s_red[tid] = s*expf(m-M);
            __syncthreads();
            for(int off=64;off>0;off>>=1){
                if(i0<off) s_red[tid] += s_red[tid+off];
                __syncthreads();
            }
            if(i0==0) s_S4[b] = s_red[b*128];
            __syncthreads();
            for(int off=64;off>0;off>>=1){
                if(i0<off) merge4(tvv, tii, tid, tid+off);
                __syncthreads();
            }
            if(i0<4){
                int base = (b*128)*4;
                s_tpv[b*4+i0] = tvv[base+i0] - M - logf(s_S4[b]);
                s_tiv[b*4+i0] = tii[base+i0];
            }
            __syncthreads();
            if(tid==0){
                float cand[16]; bool used[16];
                #pragma unroll
                for(int i=0;i<16;i++){
                    int bb = i>>2;
                    cand[i] = (step==0 && bb>0) ? -INFINITY : (g_cum[bb] + s_tpv[i]);
                    used[i] = false;
                }
                for(int s2=0;s2<4;s2++){
                    int bsel=-1; float bval=-INFINITY;
                    for(int i=0;i<16;i++)
                        if(!used[i] && (bsel<0 || cand[i]>bval)){ bval=cand[i]; bsel=i; }
                    used[bsel]=true;
                    g_cum[s2]    = bval;
                    sh_bi[s2]    = bsel>>2;
                    sh_jj[s2]    = bsel&3;
                    sh_ss[s2]    = s_tpv[bsel];
                    sh_tok[s2]   = s_tiv[bsel];
                    g_inputs[s2] = s_tiv[bsel];
                }
            }
            __syncthreads();
            int*   st  = (int*)(s_buf + 4096);
            float* sts = s_buf + 4096 + 512;
            for(int idx=tid; idx<4*L; idx+=NT){
                int bb=idx/L, s2=idx%L;
                st[idx]  = g_tokens[bb*MAXL+s2];
                sts[idx] = g_shist[bb*MAXL+s2];
            }
            __syncthreads();
            for(int idx=tid; idx<4*L; idx+=NT){
                int bb=idx/L, s2=idx%L;
                g_tokens[bb*MAXL+s2] = (s2==step) ? sh_tok[bb] : st[sh_bi[bb]*L+s2];
                g_shist[bb*MAXL+s2]  = (s2==step) ? sh_ss[bb]  : sts[sh_bi[bb]*L+s2];
            }
            // reference: new_h = hnew[jj] — replicate exactly
            for(int idx=tid; idx<BEAM*H; idx+=NT){
                int bb = idx>>10;
                g_h[idx] = __ldcg(&g_hnew[sh_jj[bb]*H + (idx&(H-1))]);
            }
        }
        gbar(mygen);
    }

    // ===== Epilogue: best beam -> output =====================================
    if(blockIdx.x==0){
        if(tid==0){
            float bm = g_cum[0]; int bb = 0;
            for(int b=1;b<BEAM;b++) if(g_cum[b]>bm){ bm=g_cum[b]; bb=b; }
            s_best = bb;
        }
        __syncthreads();
        for(int i=tid;i<L;i+=NT){
            out[i]   = (float)g_tokens[s_best*MAXL+i];
            out[L+i] = g_shist[s_best*MAXL+i];
        }
    }
}

// ---------------- launch ------------------------------------------------------
extern "C" void kernel_launch(void* const* d_in, const int* in_sizes, int n_in,
                              void* d_out, int out_size){
    int L = out_size / 2;              // output = [tokens(L), shist(L)]
    if(L < 1)    L = 48;
    if(L > MAXL) L = MAXL;
    beam_kernel<<<GRID, NT>>>(
        (const int*)  d_in[0],
        (const float*)d_in[3],
        (const float*)d_in[4],  (const float*)d_in[5],
        (const float*)d_in[6],  (const float*)d_in[7],
        (const float*)d_in[8],  (const float*)d_in[9],
        (const float*)d_in[10], (const float*)d_in[11],
        (const float*)d_in[12], (const float*)d_in[13],
        L, (float*)d_out);
}

// round 17
// speedup vs baseline: 1.0580x; 1.0580x over previous
#include <cuda_runtime.h>
#include <math.h>

// Problem constants (fixed by the dataset instance)
#define V     32000
#define H     1024
#define H4    256
#define SLEN  256
#define MAXL  64
#define BEAM  4

#define GRID  128
#define NT    512
#define NWARP 16
#define TOTW  (GRID*NWARP)   // 2048 warps
#define NGRP  8
#define GSZ   16             // blocks per barrier group (128/8)

typedef unsigned long long u64;

// ---------------- persistent device state (no allocations) -------------------
__device__ float g_Xenc[SLEN*3*H];
__device__ float g_enc_out[SLEN*H];
__device__ float g_E2T[H*SLEN];        // E2T[j][t] = Wc_ctx[j] . enc_out[t]
__device__ float g_h[BEAM*H];
__device__ float g_hnew[BEAM*H];
__device__ float g_cc[BEAM*H];
__device__ float g_scores[BEAM*SLEN];
__device__ float g_pm[BEAM*GRID];
__device__ float g_ps[BEAM*GRID];
__device__ float g_ptv[BEAM*GRID*4];
__device__ int   g_pti[BEAM*GRID*4];
__device__ float g_cum[BEAM];          // block-0 private
__device__ int   g_inputs[BEAM];
__device__ int   g_tokens[BEAM*MAXL];
__device__ float g_shist[BEAM*MAXL];
__device__ unsigned g_grp[NGRP];
__device__ unsigned g_root;
__device__ unsigned g_gen;

// ---------------- helpers ----------------------------------------------------
__device__ __forceinline__ float wred(float v){
    #pragma unroll
    for(int o=16;o>0;o>>=1) v += __shfl_xor_sync(0xffffffffu, v, o);
    return v;
}
__device__ __forceinline__ float wmax(float v){
    #pragma unroll
    for(int o=16;o>0;o>>=1) v = fmaxf(v, __shfl_xor_sync(0xffffffffu, v, o));
    return v;
}
// packed f32x2 FMA (FFMA2 — ptxas never emits this from C++; PTX-only)
__device__ __forceinline__ void ffma2(u64 &acc, u64 a, u64 b){
    asm("fma.rn.f32x2 %0,%1,%2,%0;" : "+l"(acc) : "l"(a), "l"(b));
}
__device__ __forceinline__ float f2sum(u64 a){
    float lo, hi;
    asm("mov.b64 {%0,%1},%2;" : "=f"(lo), "=f"(hi) : "l"(a));
    return lo + hi;
}
__device__ __forceinline__ ulonglong2 as_u2(float4 v){
    union{ float4 f; ulonglong2 u; } c; c.f = v; return c.u;
}
__device__ __forceinline__ bool better(float v1,int i1,float v2,int i2){
    return (v1>v2) || (v1==v2 && i1<i2);   // jax top_k: value desc, index asc
}
__device__ __forceinline__ void ins4(float* tv,int* ti,float x,int i){
    if(better(x,i,tv[3],ti[3])){
        tv[3]=x; ti[3]=i;
        #pragma unroll
        for(int k=3;k>0;k--){
            if(better(tv[k],ti[k],tv[k-1],ti[k-1])){
                float tf=tv[k]; tv[k]=tv[k-1]; tv[k-1]=tf;
                int   t2=ti[k]; ti[k]=ti[k-1]; ti[k-1]=t2;
            }
        }
    }
}
__device__ __forceinline__ void merge4r(float* av,int* ai,const float* bv,const int* bi){
    float ov[4]; int oi[4]; int ia=0, ib=0;
    #pragma unroll
    for(int k=0;k<4;k++){
        if(better(av[ia],ai[ia],bv[ib],bi[ib])){ ov[k]=av[ia]; oi[k]=ai[ia]; ia++; }
        else                                   { ov[k]=bv[ib]; oi[k]=bi[ib]; ib++; }
    }
    #pragma unroll
    for(int k=0;k<4;k++){ av[k]=ov[k]; ai[k]=oi[k]; }
}
__device__ __forceinline__ void merge4(float* tvv,int* tii,int a,int c){
    float av[4],bv[4]; int ai[4],bi[4];
    #pragma unroll
    for(int k=0;k<4;k++){ av[k]=tvv[a*4+k]; ai[k]=tii[a*4+k];
                          bv[k]=tvv[c*4+k]; bi[k]=tii[c*4+k]; }
    merge4r(av,ai,bv,bi);
    #pragma unroll
    for(int k=0;k<4;k++){ tvv[a*4+k]=av[k]; tii[a*4+k]=ai[k]; }
}

// Two-level tree barrier, fence-free. Local generation counter in a register.
__device__ __forceinline__ void gbar(unsigned &mygen){
    __syncthreads();
    mygen++;
    if(threadIdx.x==0){
        unsigned t;
        asm volatile("atom.acq_rel.gpu.global.add.u32 %0,[%1],%2;"
                     : "=r"(t) : "l"(&g_grp[blockIdx.x & (NGRP-1)]), "r"(1u) : "memory");
        if(t == (unsigned)(GSZ-1)){
            unsigned r;
            asm volatile("atom.acq_rel.gpu.global.add.u32 %0,[%1],%2;"
                         : "=r"(r) : "l"(&g_root), "r"(1u) : "memory");
            if(r == (unsigned)(NGRP-1)){
                asm volatile("st.relaxed.gpu.global.u32 [%0],%1;"
                             :: "l"(&g_root), "r"(0u) : "memory");
                #pragma unroll
                for(int i=0;i<NGRP;i++)
                    asm volatile("st.relaxed.gpu.global.u32 [%0],%1;"
                                 :: "l"(&g_grp[i]), "r"(0u) : "memory");
                asm volatile("red.release.gpu.global.add.u32 [%0],%1;"
                             :: "l"(&g_gen), "r"(1u) : "memory");
            }
        }
        unsigned cur;
        for(;;){
            asm volatile("ld.acquire.gpu.global.u32 %0,[%1];"
                         : "=r"(cur) : "l"(&g_gen) : "memory");
            if((int)(cur - mygen) >= 0) break;
        }
    }
    __syncthreads();
}

// ---------------- the persistent kernel --------------------------------------
__global__ void __launch_bounds__(NT,1)
beam_kernel(const int* __restrict__ input_seq,
            const float* __restrict__ emb,
            const float* __restrict__ eWih, const float* __restrict__ eWhh,
            const float* __restrict__ ebih, const float* __restrict__ ebhh,
            const float* __restrict__ dWih, const float* __restrict__ dWhh,
            const float* __restrict__ dbih, const float* __restrict__ dbhh,
            const float* __restrict__ Wc,   const float* __restrict__ Wout,
            int L, float* __restrict__ out)
{
    __shared__ __align__(16) float s_buf[9472];   // 37KB multipurpose
    __shared__ float s_red[512];
    __shared__ float s_part[192];    // D1 partials
    __shared__ float s_p34[64];      // D34 partials
    __shared__ float s_d2[16];       // D2 partials
    __shared__ float s_M4[4], s_S4[4];
    __shared__ int   sh_bi[4], sh_jj[4], sh_tok[4];
    __shared__ float sh_ss[4];
    __shared__ float s_tpv[16];
    __shared__ int   s_tiv[16];
    __shared__ int   s_inp[4];
    __shared__ int   s_best;

    const int tid  = threadIdx.x;
    const int lane = tid & 31;
    const int w    = tid >> 5;                 // 0..15
    const int gw   = blockIdx.x * NWARP + w;   // 0..2047

    // capture barrier generation base (before first gbar arrival)
    unsigned mygen = 0;
    if(tid==0){
        asm volatile("ld.acquire.gpu.global.u32 %0,[%1];"
                     : "=r"(mygen) : "l"(&g_gen) : "memory");
    }

    // ===== Phase 0: g_Xenc[t][k] = emb[seq[t]] . eWih[k] + ebih[k] ==========
    {
        int tgrp  = blockIdx.x & 31;
        int kpart = blockIdx.x >> 5;
        int t0 = tgrp*8;
        for(int idx=tid; idx<8*H; idx+=NT){
            int tt = idx>>10, c = idx&(H-1);
            s_buf[idx] = emb[(size_t)input_seq[t0+tt]*H + c];
        }
        __syncthreads();
        const float4* xs4 = (const float4*)s_buf;
        int kbeg = kpart*768, kend = kbeg+768;
        for(int k=kbeg+w; k<kend; k+=NWARP){
            const float4* wr = (const float4*)(eWih + (size_t)k*H);
            float acc[8] = {0,0,0,0,0,0,0,0};
            #pragma unroll
            for(int i=0;i<8;i++){
                float4 wv = wr[lane+32*i];
                #pragma unroll
                for(int tt=0;tt<8;tt++){
                    float4 xv = xs4[tt*H4 + lane + 32*i];
                    acc[tt]=fmaf(wv.x,xv.x,acc[tt]); acc[tt]=fmaf(wv.y,xv.y,acc[tt]);
                    acc[tt]=fmaf(wv.z,xv.z,acc[tt]); acc[tt]=fmaf(wv.w,xv.w,acc[tt]);
                }
            }
            #pragma unroll
            for(int tt=0;tt<8;tt++){
                float r = wred(acc[tt]);
                if(lane==0) g_Xenc[(size_t)(t0+tt)*3*H + k] = r + ebih[k];
            }
        }
    }
    gbar(mygen);

    // ===== Encoder recurrence (warps 0-7 active; FFMA2 math) =================
    {
        const int j = blockIdx.x*8 + (w&7);
        const bool enc_act = (w < 8);
        const float4* w0 = (const float4*)(eWhh + (size_t)j*H);
        const float4* w1 = (const float4*)(eWhh + (size_t)(H+j)*H);
        const float4* w2 = (const float4*)(eWhh + (size_t)(2*H+j)*H);
        const float b0 = ebhh[j], b1 = ebhh[H+j], b2 = ebhh[2*H+j];
        float4* s_h4 = (float4*)s_buf;
        const float* s_hf = s_buf;
        float gi0 = g_Xenc[j];
        float gi1 = g_Xenc[H + j];
        float gi2 = g_Xenc[2*H + j];
        for(int t=0;t<SLEN;t++){
            if(tid < 256){
                if(t==0) s_h4[tid] = make_float4(0.f,0.f,0.f,0.f);
                else     s_h4[tid] = __ldcg(((const float4*)(g_enc_out + (size_t)(t-1)*H)) + tid);
            }
            __syncthreads();
            if(enc_act){
                u64 A0=0, A1=0, A2=0;
                #pragma unroll
                for(int k=0;k<8;k++){
                    int i = lane + 32*k;
                    ulonglong2 hv = as_u2(s_h4[i]);
                    ulonglong2 v0 = as_u2(w0[i]);
                    ulonglong2 v1 = as_u2(w1[i]);
                    ulonglong2 v2 = as_u2(w2[i]);
                    ffma2(A0,v0.x,hv.x); ffma2(A0,v0.y,hv.y);
                    ffma2(A1,v1.x,hv.x); ffma2(A1,v1.y,hv.y);
                    ffma2(A2,v2.x,hv.x); ffma2(A2,v2.y,hv.y);
                }
                float a0 = wred(f2sum(A0));
                float a1 = wred(f2sum(A1));
                float a2 = wred(f2sum(A2));
                if(lane==0){
                    float hp = s_hf[j];
                    float r = 1.f/(1.f+expf(-(gi0 + a0 + b0)));
                    float z = 1.f/(1.f+expf(-(gi1 + a1 + b1)));
                    float n = tanhf(gi2 + r*(a2 + b2));
                    g_enc_out[(size_t)t*H + j] = (1.f-z)*n + z*hp;
                }
            }
            float n0=0.f, n1=0.f, n2=0.f;
            if(t+1<SLEN){
                n0 = g_Xenc[(size_t)(t+1)*3*H + j];
                n1 = g_Xenc[(size_t)(t+1)*3*H + H + j];
                n2 = g_Xenc[(size_t)(t+1)*3*H + 2*H + j];
            }
            gbar(mygen);
            gi0=n0; gi1=n1; gi2=n2;
        }
    }

    // ===== E2T precompute: E2T[j][t] = Wc_ctx[j] . enc_out[t] ===============
    {
        const int j = blockIdx.x*8 + (w&7);
        const int tt0 = (w>>3)*4;
        const float4* wr = (const float4*)(Wc + (size_t)j*2*H + H);
        for(int tile=0; tile<32; tile++){
            for(int i4=tid; i4<2048; i4+=NT)
                ((float4*)s_buf)[i4] =
                    __ldcg(((const float4*)(g_enc_out + (size_t)tile*8*H)) + i4);
            __syncthreads();
            #pragma unroll
            for(int q=0; q<4; q++){
                int tt = tt0 + q;
                const float4* er = ((const float4*)s_buf) + tt*256;
                float a = 0.f;
                #pragma unroll
                for(int k=0;k<8;k++){
                    int i = lane + 32*k;
                    float4 wv = wr[i], ev = er[i];
                    a=fmaf(wv.x,ev.x,a); a=fmaf(wv.y,ev.y,a);
                    a=fmaf(wv.z,ev.z,a); a=fmaf(wv.w,ev.w,a);
                }
                a = wred(a);
                if(lane==0) g_E2T[(size_t)j*SLEN + tile*8 + tt] = a;
            }
            __syncthreads();
        }
    }

    // ===== Init beam state ==================================================
    {
        int idx = blockIdx.x*NT + tid;
        if(idx < BEAM*H) g_h[idx] = __ldcg(&g_enc_out[(size_t)(SLEN-1)*H + (idx&(H-1))]);
        if(blockIdx.x==0 && tid<BEAM){ g_cum[tid]=0.f; g_inputs[tid]=1; /*SOS*/ }
    }
    gbar(mygen);

    // ===== Decoder loop =====================================================
    for(int step=0; step<L; step++){
        // ---- D1: GRU cell, warp-pair split, FFMA2 math ----------------------
        {
            if(tid<4) s_inp[tid] = __ldcg(&g_inputs[tid]);
            __syncthreads();
            float4* s_x4 = (float4*)s_buf;
            float4* s_h4 = ((float4*)s_buf) + 1024;
            for(int i4=tid; i4<1024; i4+=NT){
                int b = i4>>8, c = i4&255;
                s_x4[i4] = ((const float4*)(emb + (size_t)s_inp[b]*H))[c];
                s_h4[i4] = __ldcg(((const float4*)g_h) + i4);
            }
            __syncthreads();
            const int jl = w&7;
            const int j  = blockIdx.x*8 + jl;
            const int half = w>>3;
            const float* Wsrc = half ? dWhh : dWih;
            const float4* src = half ? s_h4 : s_x4;
            const float4* r0 = (const float4*)(Wsrc + (size_t)j*H);
            const float4* r1 = (const float4*)(Wsrc + (size_t)(H+j)*H);
            const float4* r2 = (const float4*)(Wsrc + (size_t)(2*H+j)*H);
            u64 A0[4]={0,0,0,0}, A1[4]={0,0,0,0}, A2[4]={0,0,0,0};
            #pragma unroll
            for(int k=0;k<8;k++){
                int i = lane + 32*k;
                ulonglong2 u0=as_u2(r0[i]), u1=as_u2(r1[i]), u2=as_u2(r2[i]);
                #pragma unroll
                for(int b=0;b<4;b++){
                    ulonglong2 xv = as_u2(src[b*256+i]);
                    ffma2(A0[b],u0.x,xv.x); ffma2(A0[b],u0.y,xv.y);
                    ffma2(A1[b],u1.x,xv.x); ffma2(A1[b],u1.y,xv.y);
                    ffma2(A2[b],u2.x,xv.x); ffma2(A2[b],u2.y,xv.y);
                }
            }
            float a0[4], a1[4], a2[4];
            #pragma unroll
            for(int b=0;b<4;b++){
                a0[b]=wred(f2sum(A0[b])); a1[b]=wred(f2sum(A1[b])); a2[b]=wred(f2sum(A2[b]));
            }
            if(lane==0){
                int base = jl*24 + half*12;
                #pragma unroll
                for(int b=0;b<4;b++){
                    s_part[base +      b] = a0[b];
                    s_part[base + 4  + b] = a1[b];
                    s_part[base + 8  + b] = a2[b];
                }
            }
            __syncthreads();
            if(tid < 32){
                int jl2 = tid>>2, b = tid&3;
                int j2 = blockIdx.x*8 + jl2;
                int ib = jl2*24, hb = jl2*24+12;
                float gi0 = s_part[ib+b]      + dbih[j2];
                float gi1 = s_part[ib+4+b]    + dbih[H+j2];
                float gi2 = s_part[ib+8+b]    + dbih[2*H+j2];
                float gh0 = s_part[hb+b]      + dbhh[j2];
                float gh1 = s_part[hb+4+b]    + dbhh[H+j2];
                float gh2 = s_part[hb+8+b]    + dbhh[2*H+j2];
                float r = 1.f/(1.f+expf(-(gi0+gh0)));
                float z = 1.f/(1.f+expf(-(gi1+gh1)));
                float n = tanhf(gi2 + r*gh2);
                float hp = s_buf[4096 + b*1024 + j2];
                g_hnew[b*H+j2] = (1.f-z)*n + z*hp;
            }
        }
        gbar(mygen);
        // ---- D2: attention scores. 2 warps per (b,t), half-dot each --------
        {
            for(int i4=tid; i4<1024; i4+=NT)
                ((float4*)s_buf)[i4] = __ldcg(((const float4*)g_hnew) + i4);
            __syncthreads();
            int task = blockIdx.x*8 + (w&7);
            int b = task>>8, t = task&(SLEN-1);
            int half = w>>3;
            const float4* hn = ((const float4*)s_buf) + b*256;
            const float4* ev = (const float4*)(g_enc_out + (size_t)t*H);
            float s = 0.f;
            #pragma unroll
            for(int kk=0;kk<4;kk++){
                int i = lane + 32*(half*4 + kk);
                float4 a = hn[i]; float4 e = ev[i];
                s=fmaf(a.x,e.x,s); s=fmaf(a.y,e.y,s);
                s=fmaf(a.z,e.z,s); s=fmaf(a.w,e.w,s);
            }
            s = wred(s);
            if(lane==0) s_d2[w] = s;
            __syncthreads();
            if(w<8 && lane==0) g_scores[task] = s_d2[w] + s_d2[w+8];
        }
        gbar(mygen);
        // ---- D34: softmax (warps 0-3) + cc split across warp pairs ---------
        {
            float4* s_hn4 = (float4*)s_buf;
            float*  s_at  = s_buf + 4096;
            for(int i4=tid; i4<1024; i4+=NT)
                s_hn4[i4] = __ldcg(((const float4*)g_hnew) + i4);
            if(w < 4){
                int b = w;
                float x[8]; float m = -INFINITY;
                #pragma unroll
                for(int q=0;q<8;q++){
                    x[q] = __ldcg(&g_scores[b*SLEN + lane + 32*q]);
                    m = fmaxf(m, x[q]);
                }
                m = wmax(m);
                float ssum = 0.f; float e[8];
                #pragma unroll
                for(int q=0;q<8;q++){ e[q] = expf(x[q]-m); ssum += e[q]; }
                ssum = wred(ssum);
                float inv = 1.f/ssum;
                #pragma unroll
                for(int q=0;q<8;q++) s_at[b*SLEN + lane + 32*q] = e[q]*inv;
            }
            __syncthreads();
            const int jl = w&7;
            const int j  = blockIdx.x*8 + jl;
            const int half = w>>3;
            const float4* wh = (const float4*)(Wc + (size_t)j*2*H);
            const float4* e2 = (const float4*)(g_E2T + (size_t)j*SLEN);
            const float4* at4 = (const float4*)s_at;
            float acc[4] = {0,0,0,0};
            if(half==0){
                #pragma unroll
                for(int k=0;k<5;k++){
                    int i = lane + 32*k;
                    float4 wl = wh[i];
                    #pragma unroll
                    for(int b=0;b<4;b++){
                        float4 hv = s_hn4[b*256+i];
                        acc[b]=fmaf(wl.x,hv.x,acc[b]); acc[b]=fmaf(wl.y,hv.y,acc[b]);
                        acc[b]=fmaf(wl.z,hv.z,acc[b]); acc[b]=fmaf(wl.w,hv.w,acc[b]);
                    }
                }
            }else{
                #pragma unroll
                for(int k=5;k<8;k++){
                    int i = lane + 32*k;
                    float4 wl = wh[i];
                    #pragma unroll
                    for(int b=0;b<4;b++){
                        float4 hv = s_hn4[b*256+i];
                        acc[b]=fmaf(wl.x,hv.x,acc[b]); acc[b]=fmaf(wl.y,hv.y,acc[b]);
                        acc[b]=fmaf(wl.z,hv.z,acc[b]); acc[b]=fmaf(wl.w,hv.w,acc[b]);
                    }
                }
                #pragma unroll
                for(int k=0;k<2;k++){
                    int i = lane + 32*k;
                    float4 ev = e2[i];
                    #pragma unroll
                    for(int b=0;b<4;b++){
                        float4 av = at4[b*64+i];
                        acc[b]=fmaf(ev.x,av.x,acc[b]); acc[b]=fmaf(ev.y,av.y,acc[b]);
                        acc[b]=fmaf(ev.z,av.z,acc[b]); acc[b]=fmaf(ev.w,av.w,acc[b]);
                    }
                }
            }
            #pragma unroll
            for(int b=0;b<4;b++) acc[b] = wred(acc[b]);
            if(lane==0){
                #pragma unroll
                for(int b=0;b<4;b++) s_p34[w*4+b] = acc[b];
            }
            __syncthreads();
            if(w<8 && lane<4)
                g_cc[lane*H + j] = tanhf(s_p34[w*4+lane] + s_p34[(w+8)*4+lane]);
        }
        gbar(mygen);
        // ---- D5: logits GEMV, __ldcs stream, FFMA2 math ---------------------
        for(int i4=tid; i4<BEAM*H4; i4+=NT)
            ((float4*)s_buf)[i4] = __ldcg(((const float4*)g_cc)+i4);
        __syncthreads();
        {
            const float4* c0 = (const float4*)s_buf;
            const float4* c1 = c0 + H4;
            const float4* c2 = c0 + 2*H4;
            const float4* c3 = c0 + 3*H4;
            float* s_lg = s_buf + 4096;
            int*   s_vi = (int*)(s_buf + 5120);
            for(int p=0;p<8;p++){
                int va = gw + p*(2*TOTW);
                int vb = va + TOTW;
                bool hasB = (vb < V);
                const float4* wa = (const float4*)(Wout + (size_t)va*H);
                const float4* wb = (const float4*)(Wout + (size_t)(hasB ? vb : va)*H);
                float4 A[8], B[8];
                #pragma unroll
                for(int k=0;k<8;k++) A[k] = __ldcs(wa + lane + 32*k);
                #pragma unroll
                for(int k=0;k<8;k++) B[k] = __ldcs(wb + lane + 32*k);
                u64 A0=0,A1=0,A2=0,A3=0, E0=0,E1=0,E2=0,E3=0;
                #pragma unroll
                for(int k=0;k<8;k++){
                    int i = lane + 32*k;
                    ulonglong2 u  = as_u2(A[k]);
                    ulonglong2 vv = as_u2(B[k]);
                    ulonglong2 X0 = as_u2(c0[i]);
                    ulonglong2 X1 = as_u2(c1[i]);
                    ulonglong2 X2 = as_u2(c2[i]);
                    ulonglong2 X3 = as_u2(c3[i]);
                    ffma2(A0,u.x,X0.x); ffma2(A0,u.y,X0.y);
                    ffma2(A1,u.x,X1.x); ffma2(A1,u.y,X1.y);
                    ffma2(A2,u.x,X2.x); ffma2(A2,u.y,X2.y);
                    ffma2(A3,u.x,X3.x); ffma2(A3,u.y,X3.y);
                    ffma2(E0,vv.x,X0.x); ffma2(E0,vv.y,X0.y);
                    ffma2(E1,vv.x,X1.x); ffma2(E1,vv.y,X1.y);
                    ffma2(E2,vv.x,X2.x); ffma2(E2,vv.y,X2.y);
                    ffma2(E3,vv.x,X3.x); ffma2(E3,vv.y,X3.y);
                }
                float a0=wred(f2sum(A0)), a1=wred(f2sum(A1));
                float a2=wred(f2sum(A2)), a3=wred(f2sum(A3));
                float e0=wred(f2sum(E0)), e1=wred(f2sum(E1));
                float e2=wred(f2sum(E2)), e3=wred(f2sum(E3));
                if(lane==0){
                    int sA = w*16 + 2*p, sB = sA+1;
                    s_lg[      sA]=a0; s_lg[256+sA]=a1; s_lg[512+sA]=a2; s_lg[768+sA]=a3;
                    s_vi[sA]=va;
                    if(hasB){
                        s_lg[      sB]=e0; s_lg[256+sB]=e1; s_lg[512+sB]=e2; s_lg[768+sB]=e3;
                        s_vi[sB]=vb;
                    }else{
                        s_lg[      sB]=-INFINITY; s_lg[256+sB]=-INFINITY;
                        s_lg[512+sB]=-INFINITY;   s_lg[768+sB]=-INFINITY;
                        s_vi[sB]=0x7fffffff;
                    }
                }
            }
        }
        __syncthreads();
        // block-local per-beam reduce: 128 threads/beam over 256 slots -------
        {
            int b  = tid >> 7;
            int i0 = tid & 127;
            float* s_lg = s_buf + 4096;
            int*   s_vi = (int*)(s_buf + 5120);
            float* tvv  = s_buf + 5376;
            int*   tii  = (int*)(s_buf + 7424);
            float x1v = s_lg[b*256 + i0];
            float x2v = s_lg[b*256 + i0 + 128];
            int   v1 = s_vi[i0], v2 = s_vi[i0+128];
            s_red[tid] = fmaxf(x1v, x2v); __syncthreads();
            for(int off=64;off>0;off>>=1){
                if(i0<off) s_red[tid] = fmaxf(s_red[tid], s_red[tid+off]);
                __syncthreads();
            }
            float bmax = s_red[b*128];
            __syncthreads();
            float tv[4] = {-INFINITY,-INFINITY,-INFINITY,-INFINITY};
            int   tix[4]= {0x7fffffff,0x7fffffff,0x7fffffff,0x7fffffff};
            ins4(tv, tix, x1v, v1);
            ins4(tv, tix, x2v, v2);
            s_red[tid] = expf(x1v - bmax) + expf(x2v - bmax);
            #pragma unroll
            for(int k=0;k<4;k++){ tvv[tid*4+k]=tv[k]; tii[tid*4+k]=tix[k]; }
            __syncthreads();
            for(int off=64;off>0;off>>=1){
                if(i0<off){
                    s_red[tid] += s_red[tid+off];
                    merge4(tvv, tii, tid, tid+off);
                }
                __syncthreads();
            }
            if(i0==0){
                int pidx = b*GRID + blockIdx.x;
                g_pm[pidx] = bmax;
                g_ps[pidx] = s_red[tid];
                #pragma unroll
                for(int k=0;k<4;k++){
                    g_ptv[pidx*4+k] = tvv[tid*4+k];
                    g_pti[pidx*4+k] = tii[tid*4+k];
                }
            }
        }
        gbar(mygen);
        // ---- D6+D7: block 0 merges 512 partials (1/thread) + combine -------
        if(blockIdx.x==0){
            int b  = tid >> 7;
            int i0 = tid & 127;
            float* tvv = s_buf;
            int*   tii = (int*)(s_buf + 2048);
            int pidx = b*GRID + i0;
            float m = __ldcg(&g_pm[pidx]);
            float s = __ldcg(&g_ps[pidx]);
            #pragma unroll
            for(int k=0;k<4;k++){
                tvv[tid*4+k] = __ldcg(&g_ptv[pidx*4+k]);
                tii[tid*4+k] = __ldcg(&g_pti[pidx*4+k]);
            }
            s_red[tid] = m; __syncthreads();
            for(int off=64;off>0;off>>=1){
                if(i0<off) s_red[tid] = fmaxf(s_red[tid], s_red[tid+off]);
                __syncthreads();
            }
            if(i0==0) s_M4[b] = s_red[b*128];
            __syncthreads();
            float M = s_M4[b];
            s_red[tid] = s*expf(m-M);
            __syncthreads();
            for(int off=64;off>0;off>>=1){
                if(i0<off) s_red[tid] += s_red[tid+off];
                __syncthreads();
            }
            if(i0==0) s_S4[b] = s_red[b*128];
            __syncthreads();
            for(int off=64;off>0;off>>=1){
                if(i0<off) merge4(tvv, tii, tid, tid+off);
                __syncthreads();
            }
            if(i0<4){
                int base = (b*128)*4;
                s_tpv[b*4+i0] = tvv[base+i0] - M - logf(s_S4[b]);
                s_tiv[b*4+i0] = tii[base+i0];
            }
            __syncthreads();
            if(tid==0){
                float cand[16]; bool used[16];
                #pragma unroll
                for(int i=0;i<16;i++){
                    int bb = i>>2;
                    cand[i] = (step==0 && bb>0) ? -INFINITY : (g_cum[bb] + s_tpv[i]);
                    used[i] = false;
                }
                for(int s2=0;s2<4;s2++){
                    int bsel=-1; float bval=-INFINITY;
                    for(int i=0;i<16;i++)
                        if(!used[i] && (bsel<0 || cand[i]>bval)){ bval=cand[i]; bsel=i; }
                    used[bsel]=true;
                    g_cum[s2]    = bval;
                    sh_bi[s2]    = bsel>>2;
                    sh_jj[s2]    = bsel&3;
                    sh_ss[s2]    = s_tpv[bsel];
                    sh_tok[s2]   = s_tiv[bsel];
                    g_inputs[s2] = s_tiv[bsel];
                }
            }
            __syncthreads();
            int*   st  = (int*)(s_buf + 4096);
            float* sts = s_buf + 4096 + 512;
            for(int idx=tid; idx<4*L; idx+=NT){
                int bb=idx/L, s2=idx%L;
                st[idx]  = g_tokens[bb*MAXL+s2];
                sts[idx] = g_shist[bb*MAXL+s2];
            }
            __syncthreads();
            for(int idx=tid; idx<4*L; idx+=NT){
                int bb=idx/L, s2=idx%L;
                g_tokens[bb*MAXL+s2] = (s2==step) ? sh_tok[bb] : st[sh_bi[bb]*L+s2];
                g_shist[bb*MAXL+s2]  = (s2==step) ? sh_ss[bb]  : sts[sh_bi[bb]*L+s2];
            }
            // reference: new_h = hnew[jj] — replicate exactly
            for(int idx=tid; idx<BEAM*H; idx+=NT){
                int bb = idx>>10;
                g_h[idx] = __ldcg(&g_hnew[sh_jj[bb]*H + (idx&(H-1))]);
            }
        }
        gbar(mygen);
    }

    // ===== Epilogue: best beam -> output =====================================
    if(blockIdx.x==0){
        if(tid==0){
            float bm = g_cum[0]; int bb = 0;
            for(int b=1;b<BEAM;b++) if(g_cum[b]>bm){ bm=g_cum[b]; bb=b; }
            s_best = bb;
        }
        __syncthreads();
        for(int i=tid;i<L;i+=NT){
            out[i]   = (float)g_tokens[s_best*MAXL+i];
            out[L+i] = g_shist[s_best*MAXL+i];
        }
    }
}

// ---------------- launch ------------------------------------------------------
extern "C" void kernel_launch(void* const* d_in, const int* in_sizes, int n_in,
                              void* d_out, int out_size){
    int L = out_size / 2;              // output = [tokens(L), shist(L)]
    if(L < 1)    L = 48;
    if(L > MAXL) L = MAXL;
    beam_kernel<<<GRID, NT>>>(
        (const int*)  d_in[0],
        (const float*)d_in[3],
        (const float*)d_in[4],  (const float*)d_in[5],
        (const float*)d_in[6],  (const float*)d_in[7],
        (const float*)d_in[8],  (const float*)d_in[9],
        (const float*)d_in[10], (const float*)d_in[11],
        (const float*)d_in[12], (const float*)d_in[13],
        L, (float*)d_out);
}